// round 7
// baseline (speedup 1.0000x reference)
#include <cuda_runtime.h>

typedef unsigned long long ull;

#define BB 256
#define TT 2048
#define TB (TT * BB)

// b-major everywhere: token m = b*TT + t
// layer-0 output: g_h1[(b*TT + t)*64 + dir*32 + cell]
__device__ float g_h1[(size_t)TB * 64];
// gate bases, INTERLEAVED: g_xg[((dir*BB + b)*TT + t)*128 + 4*cell + gate]
// gate order (i,f,g,o)
__device__ float g_xg[(size_t)2 * TB * 128];

__device__ __forceinline__ float tanh_hw(float x) {
    float y;
    asm("tanh.approx.f32 %0, %1;" : "=f"(y) : "f"(x));
    return y;
}
__device__ __forceinline__ float sigh(float x) {
    return fmaf(tanh_hw(0.5f * x), 0.5f, 0.5f);
}
__device__ __forceinline__ ull pack2(float lo, float hi) {
    ull r;
    asm("mov.b64 %0, {%1, %2};" : "=l"(r) : "f"(lo), "f"(hi));
    return r;
}
__device__ __forceinline__ void unpack2(ull v, float& lo, float& hi) {
    asm("mov.b64 {%0, %1}, %2;" : "=f"(lo), "=f"(hi) : "l"(v));
}
__device__ __forceinline__ ull ffma2(ull a, ull b, ull c) {
    ull d;
    asm("fma.rn.f32x2 %0, %1, %2, %3;" : "=l"(d) : "l"(a), "l"(b), "l"(c));
    return d;
}
__device__ __forceinline__ ull fadd2(ull a, ull b) {
    ull d;
    asm("add.rn.f32x2 %0, %1, %2;" : "=l"(d) : "l"(a), "l"(b));
    return d;
}

// ---------------------------------------------------------------------------
// Precompute xg. 256 threads = 4 token-groups x 64 row-threads. Thread rq:
// half = rq>>5 (0 -> {i,f} rows cell,32+cell ; 1 -> {g,o} rows 64+cell,96+cell),
// cell = rq&31. Emits float2 at interleaved col 4*cell + 2*half.
// ---------------------------------------------------------------------------
template<int F, bool L0>
__global__ __launch_bounds__(256)
void precompute(const float* __restrict__ oseq,  // [B,T,16] (L0 only)
                const float* __restrict__ iseq,  // [B,T,16] (L0 only)
                const float* __restrict__ Wih,   // [2,128,F]
                const float* __restrict__ bih,
                const float* __restrict__ bhh)
{
    constexpr int TM = 1024 / F;   // tokens per tile
    constexpr int TG = TM / 4;     // tokens per group
    const int dir  = blockIdx.y;
    const int tid  = threadIdx.x;
    const int rq   = tid & 63;
    const int grp  = tid >> 6;
    const int half = rq >> 5;
    const int cell = rq & 31;
    const int row0 = half * 64 + cell;        // i or g row
    const int row1 = half * 64 + 32 + cell;   // f or o row

    ull w0[F / 2], w1[F / 2];
    {
        const ull* p0 = (const ull*)(Wih + (size_t)(dir * 128 + row0) * F);
        const ull* p1 = (const ull*)(Wih + (size_t)(dir * 128 + row1) * F);
        #pragma unroll
        for (int k = 0; k < F / 2; k++) { w0[k] = p0[k]; w1[k] = p1[k]; }
    }
    const float bias0 = bih[dir * 128 + row0] + bhh[dir * 128 + row0];
    const float bias1 = bih[dir * 128 + row1] + bhh[dir * 128 + row1];
    const int ocol = 4 * cell + 2 * half;

    __shared__ __align__(16) float x_sh[2][TM][F];

    const int stride = gridDim.x * TM;
    const int srow = tid / (F / 4);
    const int sseg = tid % (F / 4);

    auto stage = [&](int m0, int buf) {
        const int m = m0 + srow;
        const int t = m & (TT - 1);
        const int bb = m >> 11;
        float4 v;
        if (L0) {
            if (sseg < 4) v = *(const float4*)&oseq[((size_t)bb * TT + t) * 16 + sseg * 4];
            else          v = *(const float4*)&iseq[((size_t)bb * TT + (TT - 1 - t)) * 16 + (sseg - 4) * 4];
        } else {
            v = *(const float4*)&g_h1[(size_t)m * 64 + sseg * 4];
        }
        *(float4*)&x_sh[buf][srow][sseg * 4] = v;
    };

    int buf = 0;
    int m0 = blockIdx.x * TM;
    if (m0 < TB) stage(m0, 0);

    float* const xg = g_xg + (size_t)dir * TB * 128;

    for (; m0 < TB; m0 += stride) {
        __syncthreads();
        const int mn = m0 + stride;
        if (mn < TB) stage(mn, buf ^ 1);

        ull a0[TG], a1[TG];
        #pragma unroll
        for (int i = 0; i < TG; i++) { a0[i] = 0ull; a1[i] = 0ull; }

        const ulonglong2* xp = (const ulonglong2*)&x_sh[buf][grp * TG][0];
        #pragma unroll
        for (int j = 0; j < F / 4; j++) {
            #pragma unroll
            for (int i = 0; i < TG; i++) {
                const ulonglong2 v = xp[i * (F / 4) + j];
                a0[i] = ffma2(w0[2 * j],     v.x, a0[i]);
                a0[i] = ffma2(w0[2 * j + 1], v.y, a0[i]);
                a1[i] = ffma2(w1[2 * j],     v.x, a1[i]);
                a1[i] = ffma2(w1[2 * j + 1], v.y, a1[i]);
            }
        }

        #pragma unroll
        for (int i = 0; i < TG; i++) {
            float lo, hi;
            float2 o;
            unpack2(a0[i], lo, hi);
            o.x = (lo + hi) + bias0;
            unpack2(a1[i], lo, hi);
            o.y = (lo + hi) + bias1;
            *(float2*)&xg[(size_t)(m0 + grp * TG + i) * 128 + ocol] = o;
        }
        buf ^= 1;
    }
}

// ---------------------------------------------------------------------------
// Recurrent: ONE chain per warp, 4 warps/block. Lane l owns cell l (all 4
// gate rows l, 32+l, 64+l, 96+l). One coalesced LDG.128/step for xg
// (interleaved layout), prefetched 4 deep. h exchange: STS.32 + syncwarp +
// LDS.128 (no cross-warp barriers). HW tanh for all activations.
// ---------------------------------------------------------------------------
template<bool L0K>
__global__ __launch_bounds__(128)
void recurrent(const float* __restrict__ Whh,   // [2,128,32]
               float* __restrict__ outp)        // L1: d_out [B,T,64]
{
    const int dir  = blockIdx.y;
    const int warp = threadIdx.x >> 5;
    const int lane = threadIdx.x & 31;
    const int b    = blockIdx.x * 4 + warp;

    ull w[4][16];
    #pragma unroll
    for (int g = 0; g < 4; g++) {
        const ull* p = (const ull*)(Whh + (size_t)(dir * 128 + g * 32 + lane) * 32);
        #pragma unroll
        for (int k = 0; k < 16; k++) w[g][k] = p[k];
    }

    __shared__ __align__(16) float h_sh[4][32];
    h_sh[warp][lane] = 0.0f;
    float c = 0.0f;
    __syncwarp();

    const float* xbase = g_xg + ((size_t)(dir * BB + b) * TT + (dir ? TT - 1 : 0)) * 128
                       + lane * 4;
    const long long stp = dir ? -128 : 128;

    float4 xf[4];
    #pragma unroll
    for (int d = 0; d < 4; d++)
        xf[d] = *(const float4*)(xbase + (long long)d * stp);

    float* const hout = L0K ? g_h1 : outp;
    const size_t orow = (size_t)b * TT;
    const int obase = dir * 32 + lane;

    for (int s = 0; s < TT; s += 4) {
        #pragma unroll
        for (int d = 0; d < 4; d++) {
            const int ss = s + d;
            const float4 x4 = xf[d];
            if (ss + 4 < TT)
                xf[d] = *(const float4*)(xbase + (long long)(ss + 4) * stp);

            const ulonglong2* hp = (const ulonglong2*)h_sh[warp];
            ull aA0 = pack2(x4.x, 0.0f), aB0 = 0ull;
            ull aA1 = pack2(x4.y, 0.0f), aB1 = 0ull;
            ull aA2 = pack2(x4.z, 0.0f), aB2 = 0ull;
            ull aA3 = pack2(x4.w, 0.0f), aB3 = 0ull;
            #pragma unroll
            for (int k = 0; k < 8; k++) {
                const ulonglong2 hv = hp[k];
                aA0 = ffma2(w[0][2 * k], hv.x, aA0); aB0 = ffma2(w[0][2 * k + 1], hv.y, aB0);
                aA1 = ffma2(w[1][2 * k], hv.x, aA1); aB1 = ffma2(w[1][2 * k + 1], hv.y, aB1);
                aA2 = ffma2(w[2][2 * k], hv.x, aA2); aB2 = ffma2(w[2][2 * k + 1], hv.y, aB2);
                aA3 = ffma2(w[3][2 * k], hv.x, aA3); aB3 = ffma2(w[3][2 * k + 1], hv.y, aB3);
            }
            float lo, hi, gi, gf, gg, go;
            ull s0 = fadd2(aA0, aB0); unpack2(s0, lo, hi); gi = lo + hi;
            ull s1 = fadd2(aA1, aB1); unpack2(s1, lo, hi); gf = lo + hi;
            ull s2 = fadd2(aA2, aB2); unpack2(s2, lo, hi); gg = lo + hi;
            ull s3 = fadd2(aA3, aB3); unpack2(s3, lo, hi); go = lo + hi;

            const float fi = sigh(gi);
            const float ff = sigh(gf);
            const float tg = tanh_hw(gg);
            const float fo = sigh(go);
            c = fmaf(ff, c, fi * tg);
            const float h = fo * tanh_hw(c);
            h_sh[warp][lane] = h;
            __syncwarp();

            const int t = dir ? (TT - 1 - ss) : ss;
            hout[(orow + t) * 64 + obase] = h;
        }
    }
}

extern "C" void kernel_launch(void* const* d_in, const int* in_sizes, int n_in,
                              void* d_out, int out_size) {
    (void)in_sizes; (void)n_in; (void)out_size;
    const float* oseq = (const float*)d_in[0];
    const float* iseq = (const float*)d_in[1];
    const float* Wih0 = (const float*)d_in[2];
    const float* Whh0 = (const float*)d_in[3];
    const float* bih0 = (const float*)d_in[4];
    const float* bhh0 = (const float*)d_in[5];
    const float* Wih1 = (const float*)d_in[6];
    const float* Whh1 = (const float*)d_in[7];
    const float* bih1 = (const float*)d_in[8];
    const float* bhh1 = (const float*)d_in[9];
    float* out = (float*)d_out;

    precompute<32, true ><<<dim3(148, 2), 256>>>(oseq, iseq, Wih0, bih0, bhh0);
    recurrent<true ><<<dim3(64, 2), 128>>>(Whh0, nullptr);
    precompute<64, false><<<dim3(148, 2), 256>>>(nullptr, nullptr, Wih1, bih1, bhh1);
    recurrent<false><<<dim3(64, 2), 128>>>(Whh1, out);
}

// round 8
// speedup vs baseline: 1.6258x; 1.6258x over previous
#include <cuda_runtime.h>

typedef unsigned long long ull;

#define BB 256
#define TT 2048

// layer-0 output: g_h1[(b*TT + t)*64 + dir*32 + cell]
__device__ float g_h1[(size_t)BB * TT * 64];

__device__ __forceinline__ float tanh_hw(float x) {
    float y;
    asm("tanh.approx.f32 %0, %1;" : "=f"(y) : "f"(x));
    return y;
}
__device__ __forceinline__ float sigh(float x) {
    return fmaf(tanh_hw(0.5f * x), 0.5f, 0.5f);
}
__device__ __forceinline__ ull pack2(float lo, float hi) {
    ull r;
    asm("mov.b64 %0, {%1, %2};" : "=l"(r) : "f"(lo), "f"(hi));
    return r;
}
__device__ __forceinline__ void unpack2(ull v, float& lo, float& hi) {
    asm("mov.b64 {%0, %1}, %2;" : "=f"(lo), "=f"(hi) : "l"(v));
}
__device__ __forceinline__ ull ffma2(ull a, ull b, ull c) {
    ull d;
    asm("fma.rn.f32x2 %0, %1, %2, %3;" : "=l"(d) : "l"(a), "l"(b), "l"(c));
    return d;
}
__device__ __forceinline__ ull fadd2(ull a, ull b) {
    ull d;
    asm("add.rn.f32x2 %0, %1, %2;" : "=l"(d) : "l"(a), "l"(b));
    return d;
}

#define BAR96() asm volatile("bar.sync 0, 96;" ::: "memory")

// ---------------------------------------------------------------------------
// Fused layer: one block = one (batch, dir) chain, 3 warps.
//   warp0: consumer (recurrence, W_hh in regs)
//   warp1: producer of gates {i,f} (W_ih rows 0..63 in regs)
//   warp2: producer of gates {g,o} (W_ih rows 64..127 in regs)
// Producers compute xg[s+1] = W_ih.x_{s+1} + b into double-buffered smem while
// the consumer runs step s. Raw x is prefetched 8 steps deep in producer regs.
// ---------------------------------------------------------------------------
template<int F, bool L0>
__global__ __launch_bounds__(96)
void lstm_fused(const float* __restrict__ oseq,   // [B,T,16] (L0)
                const float* __restrict__ iseq,   // [B,T,16] (L0)
                const float* __restrict__ Wih,    // [2,128,F]
                const float* __restrict__ Whh,    // [2,128,32]
                const float* __restrict__ bih,    // [2,128]
                const float* __restrict__ bhh,    // [2,128]
                float* __restrict__ outp)         // L1: d_out [B,T,64]
{
    const int dir  = blockIdx.y;
    const int b    = blockIdx.x;
    const int wid  = threadIdx.x >> 5;
    const int lane = threadIdx.x & 31;

    __shared__ __align__(16) float x_sh[2][F];
    __shared__ __align__(16) float xg_sh[2][32][4];   // [buf][cell][gate i,f,g,o]
    __shared__ __align__(16) float h_sh[32];

    if (wid == 0) {
        // ================= consumer =================
        ull w[4][16];
        #pragma unroll
        for (int g = 0; g < 4; g++) {
            const ull* p = (const ull*)(Whh + (size_t)(dir * 128 + g * 32 + lane) * 32);
            #pragma unroll
            for (int k = 0; k < 16; k++) w[g][k] = p[k];
        }
        h_sh[lane] = 0.0f;
        float c = 0.0f;

        BAR96();   // (1) producers staged x[0], x[1]
        BAR96();   // (2) xg[0] ready

        float* const hout = L0 ? g_h1 : outp;
        const size_t orow = (size_t)b * TT;
        const int ocol = dir * 32 + lane;

        for (int s = 0; s < TT; s++) {
            const int p = s & 1;
            const float4 xg4 = *(const float4*)&xg_sh[p][lane][0];

            const ulonglong2* hp = (const ulonglong2*)h_sh;
            ull aA0 = 0, aB0 = 0, aA1 = 0, aB1 = 0;
            ull aA2 = 0, aB2 = 0, aA3 = 0, aB3 = 0;
            #pragma unroll
            for (int k = 0; k < 8; k++) {
                const ulonglong2 hv = hp[k];
                aA0 = ffma2(w[0][2 * k], hv.x, aA0); aB0 = ffma2(w[0][2 * k + 1], hv.y, aB0);
                aA1 = ffma2(w[1][2 * k], hv.x, aA1); aB1 = ffma2(w[1][2 * k + 1], hv.y, aB1);
                aA2 = ffma2(w[2][2 * k], hv.x, aA2); aB2 = ffma2(w[2][2 * k + 1], hv.y, aB2);
                aA3 = ffma2(w[3][2 * k], hv.x, aA3); aB3 = ffma2(w[3][2 * k + 1], hv.y, aB3);
            }
            float lo, hi, gi, gf, gg, go;
            ull s0 = fadd2(aA0, aB0); unpack2(s0, lo, hi); gi = (lo + hi) + xg4.x;
            ull s1 = fadd2(aA1, aB1); unpack2(s1, lo, hi); gf = (lo + hi) + xg4.y;
            ull s2 = fadd2(aA2, aB2); unpack2(s2, lo, hi); gg = (lo + hi) + xg4.z;
            ull s3 = fadd2(aA3, aB3); unpack2(s3, lo, hi); go = (lo + hi) + xg4.w;

            const float fi = sigh(gi);
            const float ff = sigh(gf);
            const float tg = tanh_hw(gg);
            const float fo = sigh(go);
            c = fmaf(ff, c, fi * tg);
            const float h = fo * tanh_hw(c);

            h_sh[lane] = h;
            const int ts = dir ? (TT - 1 - s) : s;
            hout[(orow + ts) * 64 + ocol] = h;
            BAR96();
        }
    } else {
        // ================= producer pw =================
        const int pw = wid - 1;                 // 0: gates i,f   1: gates g,o
        const int r0 = pw * 64 + lane;          // i or g row
        const int r1 = pw * 64 + 32 + lane;     // f or o row

        ull w0[F / 2], w1[F / 2];
        {
            const ull* p0 = (const ull*)(Wih + (size_t)(dir * 128 + r0) * F);
            const ull* p1 = (const ull*)(Wih + (size_t)(dir * 128 + r1) * F);
            #pragma unroll
            for (int k = 0; k < F / 2; k++) { w0[k] = p0[k]; w1[k] = p1[k]; }
        }
        const float bias0 = bih[dir * 128 + r0] + bhh[dir * 128 + r0];
        const float bias1 = bih[dir * 128 + r1] + bhh[dir * 128 + r1];

        const bool stager = (!L0) || (pw == 0);   // L0 needs only 32 x elems

        // x element for chain step sq (clamped), this lane's feature
        auto ldxe = [&](int sq) -> float {
            sq = sq < TT - 1 ? sq : TT - 1;
            const int ts = dir ? (TT - 1 - sq) : sq;
            if (L0) {
                if (lane < 16) return oseq[((size_t)b * TT + ts) * 16 + lane];
                else           return iseq[((size_t)b * TT + (TT - 1 - ts)) * 16 + (lane - 16)];
            } else {
                return g_h1[((size_t)b * TT + ts) * 64 + pw * 32 + lane];
            }
        };
        const int xi = L0 ? lane : (pw * 32 + lane);

        auto make_xg = [&](int buf_src, int buf_dst) {
            const ulonglong2* xp = (const ulonglong2*)x_sh[buf_src];
            ull a0 = 0, b0_ = 0, a1 = 0, b1_ = 0;
            #pragma unroll
            for (int k = 0; k < F / 4; k++) {
                const ulonglong2 xv = xp[k];
                a0  = ffma2(w0[2 * k],     xv.x, a0);
                b0_ = ffma2(w0[2 * k + 1], xv.y, b0_);
                a1  = ffma2(w1[2 * k],     xv.x, a1);
                b1_ = ffma2(w1[2 * k + 1], xv.y, b1_);
            }
            float lo, hi;
            float2 o;
            ull t0 = fadd2(a0, b0_); unpack2(t0, lo, hi); o.x = (lo + hi) + bias0;
            ull t1 = fadd2(a1, b1_); unpack2(t1, lo, hi); o.y = (lo + hi) + bias1;
            *(float2*)&xg_sh[buf_dst][lane][2 * pw] = o;
        };

        // prologue: stage x[0], x[1]; fill prefetch ring x[2..9]
        if (stager) {
            x_sh[0][xi] = ldxe(0);
            x_sh[1][xi] = ldxe(1);
        }
        float xr[8];
        #pragma unroll
        for (int d = 0; d < 8; d++) xr[d] = stager ? ldxe(2 + d) : 0.0f;

        BAR96();   // (1) x[0], x[1] visible
        make_xg(0, 0);   // xg[0]
        BAR96();   // (2) xg[0] visible

        for (int s = 0; s < TT; s += 8) {
            #pragma unroll
            for (int d = 0; d < 8; d++) {
                const int ss = s + d;
                const int p = ss & 1;
                make_xg(p ^ 1, p ^ 1);            // xg[ss+1] from x[ss+1]
                if (stager) {
                    x_sh[p][xi] = xr[d];          // stage x[ss+2]
                    xr[d] = ldxe(ss + 10);        // refill (clamped)
                }
                BAR96();
            }
        }
    }
}

extern "C" void kernel_launch(void* const* d_in, const int* in_sizes, int n_in,
                              void* d_out, int out_size) {
    (void)in_sizes; (void)n_in; (void)out_size;
    const float* oseq = (const float*)d_in[0];
    const float* iseq = (const float*)d_in[1];
    const float* Wih0 = (const float*)d_in[2];
    const float* Whh0 = (const float*)d_in[3];
    const float* bih0 = (const float*)d_in[4];
    const float* bhh0 = (const float*)d_in[5];
    const float* Wih1 = (const float*)d_in[6];
    const float* Whh1 = (const float*)d_in[7];
    const float* bih1 = (const float*)d_in[8];
    const float* bhh1 = (const float*)d_in[9];
    float* out = (float*)d_out;

    lstm_fused<32, true ><<<dim3(BB, 2), 96>>>(oseq, iseq, Wih0, Whh0, bih0, bhh0, nullptr);
    lstm_fused<64, false><<<dim3(BB, 2), 96>>>(nullptr, nullptr, Wih1, Whh1, bih1, bhh1, out);
}